// round 4
// baseline (speedup 1.0000x reference)
#include <cuda_runtime.h>
#include <cuda_bf16.h>
#include <stdint.h>

#define MAXN 50000
#define IN_DIM 16
#define HID 64
#define OUT 32

// Scratch (device globals: allocation-free per harness rules), 16B-aligned.
__device__ __align__(16) float g_deg [MAXN];
__device__ __align__(16) float g_dinv[MAXN];
__device__ __align__(16) float g_g1  [MAXN * HID];   // dinv * (x@W1)
__device__ __align__(16) float g_acc1[MAXN * HID];   // aggregated layer-1
__device__ __align__(16) float g_g2  [MAXN * OUT];   // dinv * (relu(...)@W2)

// K1: deg[i] = 1 (self loop)
__global__ void k_init_deg(int N) {
    int i = blockIdx.x * blockDim.x + threadIdx.x;
    if (i < N) g_deg[i] = 1.0f;
}

// K2: deg[dst] += 1 per edge  (edge_index is int32: JAX x64 disabled)
__global__ void k_deg_count(const int* __restrict__ dst, int E) {
    int e = blockIdx.x * blockDim.x + threadIdx.x;
    if (e < E) atomicAdd(&g_deg[dst[e]], 1.0f);
}

// K3: dinv = rsqrt(deg); g1 = dinv * (x @ W1); acc1 = g1  (self-loop init)
// block = 256 threads = 16 nodes x 16 col-groups(of 4)
__global__ void k_layer1(const float* __restrict__ x,
                         const float* __restrict__ W1, int N) {
    __shared__ float W1s[IN_DIM * HID];      // 4 KB
    __shared__ float xs[16][IN_DIM];         // 16 nodes
    int tid = threadIdx.x;
    for (int i = tid; i < IN_DIM * HID; i += 256) W1s[i] = W1[i];
    int node0 = blockIdx.x * 16;
    {
        int n = tid >> 4, k = tid & 15;
        int node = node0 + n;
        xs[n][k] = (node < N) ? x[node * IN_DIM + k] : 0.0f;
    }
    __syncthreads();

    int n    = tid >> 4;
    int c4   = (tid & 15) * 4;
    int node = node0 + n;
    if (node >= N) return;

    float dinv = rsqrtf(g_deg[node]);
    if ((tid & 15) == 0) g_dinv[node] = dinv;

    float4 a = make_float4(0.f, 0.f, 0.f, 0.f);
#pragma unroll
    for (int k = 0; k < IN_DIM; k++) {
        float xv = xs[n][k];
        float4 w = *(const float4*)&W1s[k * HID + c4];
        a.x += xv * w.x; a.y += xv * w.y; a.z += xv * w.z; a.w += xv * w.w;
    }
    a.x *= dinv; a.y *= dinv; a.z *= dinv; a.w *= dinv;
    *(float4*)&g_g1  [node * HID + c4] = a;
    *(float4*)&g_acc1[node * HID + c4] = a;
}

// K4: layer-1 scatter: acc1[dst] += g1[src]
// 16 threads/edge; float4 gather + 4 scalar atomicAdds per thread
__global__ void k_scatter64(const int* __restrict__ src,
                            const int* __restrict__ dst, int E) {
    unsigned t = blockIdx.x * blockDim.x + threadIdx.x;
    unsigned e = t >> 4;
    unsigned c = t & 15;
    if (e >= (unsigned)E) return;
    int s = src[e];
    int d = dst[e];
    float4 v = *(const float4*)&g_g1[s * HID + c * 4];
    float* p = &g_acc1[d * HID + c * 4];
    atomicAdd(p + 0, v.x);
    atomicAdd(p + 1, v.y);
    atomicAdd(p + 2, v.z);
    atomicAdd(p + 3, v.w);
}

// K5: s = relu(dinv*acc1 + b1); g2 = dinv * (s @ W2); d_out init = g2
// block = 256 threads = 32 nodes x 8 col-groups(of 4)
__global__ void k_layer2(const float* __restrict__ W2,
                         const float* __restrict__ b1,
                         float* __restrict__ out, int N) {
    __shared__ float W2s[HID * OUT];     // 8 KB
    __shared__ float ss[32][HID + 1];    // padded: conflict-free
    int tid = threadIdx.x;
    for (int i = tid; i < HID * OUT; i += 256) W2s[i] = W2[i];

    int n    = tid >> 3;
    int lane = tid & 7;
    int node = blockIdx.x * 32 + n;

    float dinv = 0.f;
    if (node < N) {
        dinv = g_dinv[node];
#pragma unroll
        for (int j = 0; j < 8; j++) {
            int col = lane * 8 + j;
            float v = dinv * g_acc1[node * HID + col] + b1[col];
            ss[n][col] = fmaxf(v, 0.0f);
        }
    }
    __syncthreads();
    if (node >= N) return;

    float4 a = make_float4(0.f, 0.f, 0.f, 0.f);
#pragma unroll
    for (int k = 0; k < HID; k++) {
        float sv = ss[n][k];
        float4 w = *(const float4*)&W2s[k * OUT + lane * 4];
        a.x += sv * w.x; a.y += sv * w.y; a.z += sv * w.z; a.w += sv * w.w;
    }
    a.x *= dinv; a.y *= dinv; a.z *= dinv; a.w *= dinv;
    *(float4*)&g_g2[node * OUT + lane * 4] = a;
    *(float4*)&out [node * OUT + lane * 4] = a;   // self-loop init
}

// K6: layer-2 scatter: out[dst] += g2[src]
// 8 threads/edge; float4 gather + 4 scalar atomicAdds per thread
__global__ void k_scatter32(const int* __restrict__ src,
                            const int* __restrict__ dst,
                            float* __restrict__ out, int E) {
    unsigned t = blockIdx.x * blockDim.x + threadIdx.x;
    unsigned e = t >> 3;
    unsigned c = t & 7;
    if (e >= (unsigned)E) return;
    int s = src[e];
    int d = dst[e];
    float4 v = *(const float4*)&g_g2[s * OUT + c * 4];
    float* p = &out[d * OUT + c * 4];
    atomicAdd(p + 0, v.x);
    atomicAdd(p + 1, v.y);
    atomicAdd(p + 2, v.z);
    atomicAdd(p + 3, v.w);
}

// K7: out = out * dinv[node] + b2   (float4 per thread)
__global__ void k_finalize(float* __restrict__ out,
                           const float* __restrict__ b2, int N) {
    int t = blockIdx.x * blockDim.x + threadIdx.x;   // N*8 threads
    if (t >= N * 8) return;
    int node = t >> 3;
    int c4   = (t & 7) * 4;
    float dinv = g_dinv[node];
    float4 v = ((float4*)out)[t];
    v.x = v.x * dinv + b2[c4 + 0];
    v.y = v.y * dinv + b2[c4 + 1];
    v.z = v.z * dinv + b2[c4 + 2];
    v.w = v.w * dinv + b2[c4 + 3];
    ((float4*)out)[t] = v;
}

extern "C" void kernel_launch(void* const* d_in, const int* in_sizes, int n_in,
                              void* d_out, int out_size) {
    const float* x   = (const float*)d_in[0];
    const int*   ei  = (const int*)d_in[1];     // int32! (JAX x64 disabled)
    const float* W1  = (const float*)d_in[2];
    const float* b1  = (const float*)d_in[3];
    const float* W2  = (const float*)d_in[4];
    const float* b2  = (const float*)d_in[5];
    float*       out = (float*)d_out;

    int N = in_sizes[0] / IN_DIM;     // 50000
    int E = in_sizes[1] / 2;          // 800000
    const int* src = ei;
    const int* dst = ei + E;

    k_init_deg <<<(N + 255) / 256, 256>>>(N);
    k_deg_count<<<(E + 255) / 256, 256>>>(dst, E);
    k_layer1   <<<(N + 15) / 16,   256>>>(x, W1, N);
    k_scatter64<<<((long long)E * 16 + 255) / 256, 256>>>(src, dst, E);
    k_layer2   <<<(N + 31) / 32,   256>>>(W2, b1, out, N);
    k_scatter32<<<((long long)E * 8 + 255) / 256, 256>>>(src, dst, out, E);
    k_finalize <<<(N * 8 + 255) / 256, 256>>>(out, b2, N);
}

// round 6
// speedup vs baseline: 1.4823x; 1.4823x over previous
#include <cuda_runtime.h>
#include <cuda_bf16.h>
#include <stdint.h>

#define MAXN 50000
#define IN_DIM 16
#define HID 64
#define OUT 32

// Scratch (device globals: allocation-free per harness rules), 16B-aligned.
__device__ __align__(16) float g_deg [MAXN];
__device__ __align__(16) float g_dinv[MAXN];
__device__ __align__(16) float g_g1  [MAXN * HID];   // dinv * (x@W1)
__device__ __align__(16) float g_acc1[MAXN * HID];   // aggregated layer-1
__device__ __align__(16) float g_g2  [MAXN * OUT];   // dinv * (relu(...)@W2)

// K1: deg[i] = 1 (self loop)
__global__ void k_init_deg(int N) {
    int i = blockIdx.x * blockDim.x + threadIdx.x;
    if (i < N) g_deg[i] = 1.0f;
}

// K2: deg[dst] += 1 per edge  (edge_index is int32: JAX x64 disabled)
__global__ void k_deg_count(const int* __restrict__ dst, int E) {
    int e = blockIdx.x * blockDim.x + threadIdx.x;
    if (e < E) atomicAdd(&g_deg[dst[e]], 1.0f);
}

// K3: dinv = rsqrt(deg); g1 = dinv * (x @ W1); acc1 = g1  (self-loop init)
// block = 256 threads = 16 nodes x 16 col-groups(of 4)
__global__ void k_layer1(const float* __restrict__ x,
                         const float* __restrict__ W1, int N) {
    __shared__ float W1s[IN_DIM * HID];      // 4 KB
    __shared__ float xs[16][IN_DIM];         // 16 nodes
    int tid = threadIdx.x;
    for (int i = tid; i < IN_DIM * HID; i += 256) W1s[i] = W1[i];
    int node0 = blockIdx.x * 16;
    {
        int n = tid >> 4, k = tid & 15;
        int node = node0 + n;
        xs[n][k] = (node < N) ? x[node * IN_DIM + k] : 0.0f;
    }
    __syncthreads();

    int n    = tid >> 4;
    int c4   = (tid & 15) * 4;
    int node = node0 + n;
    if (node >= N) return;

    float dinv = rsqrtf(g_deg[node]);
    if ((tid & 15) == 0) g_dinv[node] = dinv;

    float4 a = make_float4(0.f, 0.f, 0.f, 0.f);
#pragma unroll
    for (int k = 0; k < IN_DIM; k++) {
        float xv = xs[n][k];
        float4 w = *(const float4*)&W1s[k * HID + c4];
        a.x += xv * w.x; a.y += xv * w.y; a.z += xv * w.z; a.w += xv * w.w;
    }
    a.x *= dinv; a.y *= dinv; a.z *= dinv; a.w *= dinv;
    *(float4*)&g_g1  [node * HID + c4] = a;
    *(float4*)&g_acc1[node * HID + c4] = a;
}

// K4: layer-1 scatter: acc1[dst] += g1[src]
// 4 threads/edge; one float4 gather + one float4 vector-red per thread
__global__ void k_scatter64(const int* __restrict__ src,
                            const int* __restrict__ dst, int E) {
    unsigned t = blockIdx.x * blockDim.x + threadIdx.x;
    unsigned e = t >> 2;
    unsigned c = t & 3;
    if (e >= (unsigned)E) return;
    int s = __ldg(&src[e]);
    int d = __ldg(&dst[e]);
    float4 v = *(const float4*)&g_g1[s * HID + c * 16];
    float4 v2 = *(const float4*)&g_g1[s * HID + c * 16 + 4];
    float4 v3 = *(const float4*)&g_g1[s * HID + c * 16 + 8];
    float4 v4 = *(const float4*)&g_g1[s * HID + c * 16 + 12];
    atomicAdd((float4*)&g_acc1[d * HID + c * 16],      v);
    atomicAdd((float4*)&g_acc1[d * HID + c * 16 + 4],  v2);
    atomicAdd((float4*)&g_acc1[d * HID + c * 16 + 8],  v3);
    atomicAdd((float4*)&g_acc1[d * HID + c * 16 + 12], v4);
}

// K5: s = relu(dinv*acc1 + b1); g2 = dinv * (s @ W2); d_out init = g2
// block = 256 threads = 32 nodes x 8 col-groups(of 4)
__global__ void k_layer2(const float* __restrict__ W2,
                         const float* __restrict__ b1,
                         float* __restrict__ out, int N) {
    __shared__ float W2s[HID * OUT];     // 8 KB
    __shared__ float ss[32][HID + 1];    // padded: conflict-free
    int tid = threadIdx.x;
    for (int i = tid; i < HID * OUT; i += 256) W2s[i] = W2[i];

    int n    = tid >> 3;
    int lane = tid & 7;
    int node = blockIdx.x * 32 + n;

    float dinv = 0.f;
    if (node < N) {
        dinv = g_dinv[node];
#pragma unroll
        for (int j = 0; j < 8; j++) {
            int col = lane * 8 + j;
            float v = dinv * g_acc1[node * HID + col] + b1[col];
            ss[n][col] = fmaxf(v, 0.0f);
        }
    }
    __syncthreads();
    if (node >= N) return;

    float4 a = make_float4(0.f, 0.f, 0.f, 0.f);
#pragma unroll
    for (int k = 0; k < HID; k++) {
        float sv = ss[n][k];
        float4 w = *(const float4*)&W2s[k * OUT + lane * 4];
        a.x += sv * w.x; a.y += sv * w.y; a.z += sv * w.z; a.w += sv * w.w;
    }
    a.x *= dinv; a.y *= dinv; a.z *= dinv; a.w *= dinv;
    *(float4*)&g_g2[node * OUT + lane * 4] = a;
    *(float4*)&out [node * OUT + lane * 4] = a;   // self-loop init
}

// K6: layer-2 scatter: out[dst] += g2[src]
// 2 threads/edge; four float4 gathers/red per... -> 16 floats/thread
__global__ void k_scatter32(const int* __restrict__ src,
                            const int* __restrict__ dst,
                            float* __restrict__ out, int E) {
    unsigned t = blockIdx.x * blockDim.x + threadIdx.x;
    unsigned e = t >> 1;
    unsigned c = t & 1;
    if (e >= (unsigned)E) return;
    int s = __ldg(&src[e]);
    int d = __ldg(&dst[e]);
    float4 v  = *(const float4*)&g_g2[s * OUT + c * 16];
    float4 v2 = *(const float4*)&g_g2[s * OUT + c * 16 + 4];
    float4 v3 = *(const float4*)&g_g2[s * OUT + c * 16 + 8];
    float4 v4 = *(const float4*)&g_g2[s * OUT + c * 16 + 12];
    atomicAdd((float4*)&out[d * OUT + c * 16],      v);
    atomicAdd((float4*)&out[d * OUT + c * 16 + 4],  v2);
    atomicAdd((float4*)&out[d * OUT + c * 16 + 8],  v3);
    atomicAdd((float4*)&out[d * OUT + c * 16 + 12], v4);
}

// K7: out = out * dinv[node] + b2   (float4 per thread)
__global__ void k_finalize(float* __restrict__ out,
                           const float* __restrict__ b2, int N) {
    int t = blockIdx.x * blockDim.x + threadIdx.x;   // N*8 threads
    if (t >= N * 8) return;
    int node = t >> 3;
    int c4   = (t & 7) * 4;
    float dinv = g_dinv[node];
    float4 v = ((float4*)out)[t];
    v.x = v.x * dinv + b2[c4 + 0];
    v.y = v.y * dinv + b2[c4 + 1];
    v.z = v.z * dinv + b2[c4 + 2];
    v.w = v.w * dinv + b2[c4 + 3];
    ((float4*)out)[t] = v;
}

extern "C" void kernel_launch(void* const* d_in, const int* in_sizes, int n_in,
                              void* d_out, int out_size) {
    const float* x   = (const float*)d_in[0];
    const int*   ei  = (const int*)d_in[1];     // int32 (JAX x64 disabled)
    const float* W1  = (const float*)d_in[2];
    const float* b1  = (const float*)d_in[3];
    const float* W2  = (const float*)d_in[4];
    const float* b2  = (const float*)d_in[5];
    float*       out = (float*)d_out;

    int N = in_sizes[0] / IN_DIM;     // 50000
    int E = in_sizes[1] / 2;          // 800000
    const int* src = ei;
    const int* dst = ei + E;

    k_init_deg <<<(N + 255) / 256, 256>>>(N);
    k_deg_count<<<(E + 255) / 256, 256>>>(dst, E);
    k_layer1   <<<(N + 15) / 16,   256>>>(x, W1, N);
    k_scatter64<<<((long long)E * 4 + 255) / 256, 256>>>(src, dst, E);
    k_layer2   <<<(N + 31) / 32,   256>>>(W2, b1, out, N);
    k_scatter32<<<((long long)E * 2 + 255) / 256, 256>>>(src, dst, out, E);
    k_finalize <<<(N * 8 + 255) / 256, 256>>>(out, b2, N);
}

// round 9
// speedup vs baseline: 2.2819x; 1.5394x over previous
#include <cuda_runtime.h>
#include <cuda_bf16.h>
#include <stdint.h>

#define MAXN 50000
#define MAXE 800000
#define IN_DIM 16
#define HID 64
#define OUT 32
#define SCAN_B 256   // scan block size; NB = ceil(N/256) <= 256 required

// Scratch (device globals; allocation-free per harness rules)
__device__ __align__(16) int   g_cnt   [MAXN];
__device__ __align__(16) int   g_rowptr[MAXN + 1];
__device__ __align__(16) int   g_cursor[MAXN];
__device__ __align__(16) int   g_bsum  [SCAN_B];
__device__ __align__(16) int   g_csr   [MAXE];
__device__ __align__(16) float g_dinv  [MAXN];
__device__ __align__(16) float g_g1    [MAXN * HID];  // dinv*(x@W1)
__device__ __align__(16) float g_h     [MAXN * HID];  // relu(dinv*acc1+b1)
__device__ __align__(16) float g_g2    [MAXN * OUT];  // dinv*(h@W2)

// ---------- CSR build ----------
__global__ void k_zero(int N) {
    int i = blockIdx.x * blockDim.x + threadIdx.x;
    if (i < N) g_cnt[i] = 0;
}

__global__ void k_count(const int* __restrict__ dst, int E) {
    int e = blockIdx.x * blockDim.x + threadIdx.x;
    if (e < E) atomicAdd(&g_cnt[dst[e]], 1);
}

// per-block exclusive scan of g_cnt -> g_rowptr, block totals -> g_bsum
__global__ void k_scan1(int N) {
    __shared__ int sh[SCAN_B];
    int i = blockIdx.x * SCAN_B + threadIdx.x;
    int v = (i < N) ? g_cnt[i] : 0;
    sh[threadIdx.x] = v;
    __syncthreads();
    for (int off = 1; off < SCAN_B; off <<= 1) {
        int t = (threadIdx.x >= off) ? sh[threadIdx.x - off] : 0;
        __syncthreads();
        sh[threadIdx.x] += t;
        __syncthreads();
    }
    if (i < N) g_rowptr[i] = sh[threadIdx.x] - v;   // exclusive
    if (threadIdx.x == SCAN_B - 1) g_bsum[blockIdx.x] = sh[SCAN_B - 1];
}

// exclusive scan of block sums (single block; NB <= 256)
__global__ void k_scan2(int NB) {
    __shared__ int sh[SCAN_B];
    int v = (threadIdx.x < NB) ? g_bsum[threadIdx.x] : 0;
    sh[threadIdx.x] = v;
    __syncthreads();
    for (int off = 1; off < SCAN_B; off <<= 1) {
        int t = (threadIdx.x >= off) ? sh[threadIdx.x - off] : 0;
        __syncthreads();
        sh[threadIdx.x] += t;
        __syncthreads();
    }
    if (threadIdx.x < NB) g_bsum[threadIdx.x] = sh[threadIdx.x] - v;
}

// add block offsets; init cursor; dinv = rsqrt(cnt+1)
__global__ void k_scan3(int N, int E) {
    int i = blockIdx.x * blockDim.x + threadIdx.x;
    if (i < N) {
        int r = g_rowptr[i] + g_bsum[i >> 8];
        g_rowptr[i] = r;
        g_cursor[i] = r;
        g_dinv[i]   = rsqrtf((float)g_cnt[i] + 1.0f);
    }
    if (i == 0) g_rowptr[N] = E;
}

__global__ void k_fill(const int* __restrict__ src,
                       const int* __restrict__ dst, int E) {
    int e = blockIdx.x * blockDim.x + threadIdx.x;
    if (e < E) {
        int pos = atomicAdd(&g_cursor[dst[e]], 1);
        g_csr[pos] = src[e];
    }
}

// ---------- layer 1 GEMM: g1 = dinv * (x @ W1) ----------
// 256 threads = 16 nodes x 16 col-groups(of 4)
__global__ void k_layer1(const float* __restrict__ x,
                         const float* __restrict__ W1, int N) {
    __shared__ float W1s[IN_DIM * HID];
    __shared__ float xs[16][IN_DIM];
    int tid = threadIdx.x;
    for (int i = tid; i < IN_DIM * HID; i += 256) W1s[i] = W1[i];
    int node0 = blockIdx.x * 16;
    {
        int n = tid >> 4, k = tid & 15;
        int node = node0 + n;
        xs[n][k] = (node < N) ? x[node * IN_DIM + k] : 0.0f;
    }
    __syncthreads();

    int n    = tid >> 4;
    int c4   = (tid & 15) * 4;
    int node = node0 + n;
    if (node >= N) return;

    float dinv = g_dinv[node];
    float4 a = make_float4(0.f, 0.f, 0.f, 0.f);
#pragma unroll
    for (int k = 0; k < IN_DIM; k++) {
        float xv = xs[n][k];
        float4 w = *(const float4*)&W1s[k * HID + c4];
        a.x += xv * w.x; a.y += xv * w.y; a.z += xv * w.z; a.w += xv * w.w;
    }
    a.x *= dinv; a.y *= dinv; a.z *= dinv; a.w *= dinv;
    *(float4*)&g_g1[node * HID + c4] = a;
}

// ---------- agg1: warp per node; h = relu(dinv*(g1[self]+sum g1[src]) + b1)
__global__ void k_agg1(const float* __restrict__ b1, int N) {
    int gt   = blockIdx.x * blockDim.x + threadIdx.x;
    int node = gt >> 5;
    int lane = gt & 31;
    if (node >= N) return;

    float2 acc = *(const float2*)&g_g1[node * HID + lane * 2];  // self loop
    int beg = g_rowptr[node];
    int end = g_rowptr[node + 1];
    int j = beg;
    for (; j + 1 < end; j += 2) {
        int s0 = g_csr[j];
        int s1 = g_csr[j + 1];
        float2 v0 = *(const float2*)&g_g1[s0 * HID + lane * 2];
        float2 v1 = *(const float2*)&g_g1[s1 * HID + lane * 2];
        acc.x += v0.x + v1.x;
        acc.y += v0.y + v1.y;
    }
    if (j < end) {
        int s = g_csr[j];
        float2 v = *(const float2*)&g_g1[s * HID + lane * 2];
        acc.x += v.x; acc.y += v.y;
    }
    float dinv = g_dinv[node];
    float2 bb = *(const float2*)&b1[lane * 2];
    float2 h;
    h.x = fmaxf(acc.x * dinv + bb.x, 0.0f);
    h.y = fmaxf(acc.y * dinv + bb.y, 0.0f);
    *(float2*)&g_h[node * HID + lane * 2] = h;
}

// ---------- layer 2 GEMM: g2 = dinv * (h @ W2) ----------
// 256 threads = 32 nodes x 8 col-groups(of 4)
__global__ void k_layer2(const float* __restrict__ W2, int N) {
    __shared__ float W2s[HID * OUT];
    __shared__ float ss[32][HID + 1];
    int tid = threadIdx.x;
    for (int i = tid; i < HID * OUT; i += 256) W2s[i] = W2[i];

    int n    = tid >> 3;
    int lane = tid & 7;
    int node = blockIdx.x * 32 + n;

    if (node < N) {
#pragma unroll
        for (int j = 0; j < 8; j++) {
            int col = lane * 8 + j;
            ss[n][col] = g_h[node * HID + col];
        }
    }
    __syncthreads();
    if (node >= N) return;

    float dinv = g_dinv[node];
    float4 a = make_float4(0.f, 0.f, 0.f, 0.f);
#pragma unroll
    for (int k = 0; k < HID; k++) {
        float sv = ss[n][k];
        float4 w = *(const float4*)&W2s[k * OUT + lane * 4];
        a.x += sv * w.x; a.y += sv * w.y; a.z += sv * w.z; a.w += sv * w.w;
    }
    a.x *= dinv; a.y *= dinv; a.z *= dinv; a.w *= dinv;
    *(float4*)&g_g2[node * OUT + lane * 4] = a;
}

// ---------- agg2: warp per node; out = dinv*(g2[self]+sum g2[src]) + b2
__global__ void k_agg2(const float* __restrict__ b2,
                       float* __restrict__ out, int N) {
    int gt   = blockIdx.x * blockDim.x + threadIdx.x;
    int node = gt >> 5;
    int lane = gt & 31;
    if (node >= N) return;

    float acc = g_g2[node * OUT + lane];   // self loop
    int beg = g_rowptr[node];
    int end = g_rowptr[node + 1];
    int j = beg;
    for (; j + 1 < end; j += 2) {
        int s0 = g_csr[j];
        int s1 = g_csr[j + 1];
        acc += g_g2[s0 * OUT + lane] + g_g2[s1 * OUT + lane];
    }
    if (j < end) {
        int s = g_csr[j];
        acc += g_g2[s * OUT + lane];
    }
    out[node * OUT + lane] = acc * g_dinv[node] + b2[lane];
}

extern "C" void kernel_launch(void* const* d_in, const int* in_sizes, int n_in,
                              void* d_out, int out_size) {
    const float* x   = (const float*)d_in[0];
    const int*   ei  = (const int*)d_in[1];     // int32 (JAX x64 disabled)
    const float* W1  = (const float*)d_in[2];
    const float* b1  = (const float*)d_in[3];
    const float* W2  = (const float*)d_in[4];
    const float* b2  = (const float*)d_in[5];
    float*       out = (float*)d_out;

    int N = in_sizes[0] / IN_DIM;     // 50000
    int E = in_sizes[1] / 2;          // 800000
    const int* src = ei;
    const int* dst = ei + E;
    int NB = (N + SCAN_B - 1) / SCAN_B;   // 196 <= 256

    // NOTE: k_agg2 lane layout covers OUT=32 with one warp; HID=64 uses float2.
    k_zero  <<<(N + 255) / 256, 256>>>(N);
    k_count <<<(E + 255) / 256, 256>>>(dst, E);
    k_scan1 <<<NB, SCAN_B>>>(N);
    k_scan2 <<<1, SCAN_B>>>(NB);
    k_scan3 <<<(N + 255) / 256, 256>>>(N, E);
    k_fill  <<<(E + 255) / 256, 256>>>(src, dst, E);
    k_layer1<<<(N + 15) / 16, 256>>>(x, W1, N);
    k_agg1  <<<((long long)N * 32 + 255) / 256, 256>>>(b1, N);
    k_layer2<<<(N + 31) / 32, 256>>>(W2, N);
    k_agg2  <<<((long long)N * 32 + 255) / 256, 256>>>(b2, out, N);
}